// round 5
// baseline (speedup 1.0000x reference)
#include <cuda_runtime.h>
#include <math.h>

#define TOTAL 349525

// ---------------- constants ----------------
__constant__ int c_OFF[11]   = {0,1,5,21,85,341,1365,5461,21845,87381,349525};
__constant__ int c_SIZE[10]  = {1,4,16,64,256,1024,4096,16384,65536,262144};
__constant__ int c_embCum[11]= {0,1,2,3,4,8,24,88,344,1368,5464};

// ---------------- scratch (device globals: allocation-free) ----------------
__device__ float g_G[TOTAL * 128];   // pre-conv accumulator (in_proj + pooled)
__device__ float g_H[TOTAL * 128];   // post-conv output per level

// ---------------- Morton helpers ----------------
__device__ __forceinline__ unsigned deint(unsigned x) {
    x &= 0x55555555u;
    x = (x | (x >> 1)) & 0x33333333u;
    x = (x | (x >> 2)) & 0x0F0F0F0Fu;
    x = (x | (x >> 4)) & 0x00FF00FFu;
    x = (x | (x >> 8)) & 0x0000FFFFu;
    return x;
}
__device__ __forceinline__ unsigned inter(unsigned x) {
    x &= 0xFFFFu;
    x = (x | (x << 8)) & 0x00FF00FFu;
    x = (x | (x << 4)) & 0x0F0F0F0Fu;
    x = (x | (x << 2)) & 0x33333333u;
    x = (x | (x << 1)) & 0x55555555u;
    return x;
}

// ---------------- Stage A: pos-encode + in_proj ----------------
// 32 nodes per block, 256 threads. x(40) @ W.T(128x40) -> g_G
__global__ __launch_bounds__(256) void enc_kernel(
    const float* __restrict__ feats,
    const float* __restrict__ W,       // (128,40)
    const float* __restrict__ bias)    // (128)
{
    __shared__ float Xs[40][36];       // [k][node], padded pitch
    __shared__ float Ws[40][128];      // [k][j]
    __shared__ float px[32], py[32], pd[32];

    int tid = threadIdx.x;
    int nbase = blockIdx.x * 32;

    if (tid < 32) {
        int g = nbase + tid;
        float fx = 0.f, fy = 0.f, fd = 0.f, ff = 0.f;
        if (g < TOTAL) {
            int d = 0;
            while (d < 9 && g >= c_OFF[d + 1]) d++;
            int li = g - c_OFF[d];
            unsigned ix = deint((unsigned)li);
            unsigned iy = deint(((unsigned)li) >> 1);
            float res = (float)(1 << d);
            fx = ((float)ix + 0.5f) / res;
            fy = ((float)iy + 0.5f) / res;
            fd = (float)d / 9.0f;
            ff = feats[g];
        }
        px[tid] = fx; py[tid] = fy; pd[tid] = fd;
        Xs[0][tid] = ff; Xs[1][tid] = fx; Xs[2][tid] = fy; Xs[3][tid] = fd;
    }
    for (int idx = tid; idx < 128 * 40; idx += 256) {
        Ws[idx % 40][idx / 40] = W[idx];
    }
    __syncthreads();

    for (int idx = tid; idx < 32 * 18; idx += 256) {
        int n = idx & 31;
        int t = idx >> 5;                  // 0..17
        int comp = t / 6, f = t % 6;
        float p = (comp == 0) ? px[n] : ((comp == 1) ? py[n] : pd[n]);
        float ang = p * 6.283185307179586f * (float)(1 << f);
        float s, c;
        sincosf(ang, &s, &c);
        Xs[4 + comp * 12 + f][n]     = s;
        Xs[4 + comp * 12 + 6 + f][n] = c;
    }
    __syncthreads();

    int tn = tid & 7, tj = tid >> 3;
    int n0 = tn * 4, j0 = tj * 4;
    float acc[4][4];
#pragma unroll
    for (int i = 0; i < 4; i++)
#pragma unroll
        for (int j = 0; j < 4; j++) acc[i][j] = 0.f;

#pragma unroll
    for (int k = 0; k < 40; k++) {
        float4 x = *(const float4*)&Xs[k][n0];
        float4 w = *(const float4*)&Ws[k][j0];
        float xv[4] = {x.x, x.y, x.z, x.w};
        float wv[4] = {w.x, w.y, w.z, w.w};
#pragma unroll
        for (int i = 0; i < 4; i++)
#pragma unroll
            for (int j = 0; j < 4; j++) acc[i][j] += xv[i] * wv[j];
    }

    float b0 = bias[j0], b1 = bias[j0 + 1], b2 = bias[j0 + 2], b3 = bias[j0 + 3];
#pragma unroll
    for (int i = 0; i < 4; i++) {
        int g = nbase + n0 + i;
        if (g < TOTAL) {
            float4 o = make_float4(acc[i][0] + b0, acc[i][1] + b1,
                                   acc[i][2] + b2, acc[i][3] + b3);
            *(float4*)&g_G[g * 128 + j0] = o;
        }
    }
}

// ---------------- Stage B1: pooling ----------------
// G[dst] += mean of 4 Morton-contiguous children from src (H, or G for level 9)
__global__ __launch_bounds__(256) void pool_kernel(int dst, int srcIsG)
{
    int N = c_SIZE[dst];
    int idx = blockIdx.x * 256 + threadIdx.x;
    if (idx >= N * 32) return;
    int n = idx >> 5, c4 = idx & 31;
    const float* src = srcIsG ? g_G : g_H;
    const float* s0 = src + (c_OFF[dst + 1] + n * 4) * 128 + c4 * 4;
    float4 a = *(const float4*)(s0);
    float4 b = *(const float4*)(s0 + 128);
    float4 c = *(const float4*)(s0 + 256);
    float4 d = *(const float4*)(s0 + 384);
    float* dp = g_G + (c_OFF[dst] + n) * 128 + c4 * 4;
    float4 g = *(float4*)dp;
    g.x += 0.25f * (a.x + b.x + c.x + d.x);
    g.y += 0.25f * (a.y + b.y + c.y + d.y);
    g.z += 0.25f * (a.z + b.z + c.z + d.z);
    g.w += 0.25f * (a.w + b.w + c.w + d.w);
    *(float4*)dp = g;
}

// ---------------- Stage B2: quadconv ----------------
// H[n][j] = relu(b[j] + sum_p sum_c G[neigh(n,p)][c] * W[j][p*128+c])
// 128 nodes x 128 outs per block, K=1152 in chunks of 16, 8x8 micro-tile.
__global__ __launch_bounds__(256) void conv_kernel(
    const float* __restrict__ W,      // (128, 1152) for this level
    const float* __restrict__ bias,   // (128)
    int N, int res, int rowOff)
{
    __shared__ int   nIdx[128 * 9];
    __shared__ float Xs[16][132];     // [kk][node]
    __shared__ float Ws[16][132];     // [kk][j]

    int tid = threadIdx.x;
    int nbase = blockIdx.x * 128;

    for (int idx = tid; idx < 128 * 9; idx += 256) {
        int n = idx / 9, p = idx % 9;
        int node = nbase + n;
        int val = -1;
        if (node < N) {
            int ix = (int)deint((unsigned)node);
            int iy = (int)deint(((unsigned)node) >> 1);
            int nx = ix + (p % 3) - 1;
            int ny = iy + (p / 3) - 1;
            if (nx >= 0 && nx < res && ny >= 0 && ny < res)
                val = (int)(inter((unsigned)nx) | (inter((unsigned)ny) << 1));
        }
        nIdx[idx] = val;
    }
    __syncthreads();

    float acc[8][8];
#pragma unroll
    for (int i = 0; i < 8; i++)
#pragma unroll
        for (int j = 0; j < 8; j++) acc[i][j] = 0.f;

    int tn = tid & 15, tj = tid >> 4;
    const float* Gb = g_G + (long)rowOff * 128;

    for (int k0 = 0; k0 < 1152; k0 += 16) {
        int p = k0 >> 7, c0 = k0 & 127;
#pragma unroll
        for (int it = 0; it < 2; ++it) {
            int idx = tid + it * 256;       // 0..511
            int n = idx >> 2, kk4 = idx & 3;
            int srcn = nIdx[n * 9 + p];
            float4 v = make_float4(0.f, 0.f, 0.f, 0.f);
            if (srcn >= 0) v = *(const float4*)(Gb + srcn * 128 + c0 + kk4 * 4);
            Xs[kk4 * 4 + 0][n] = v.x;
            Xs[kk4 * 4 + 1][n] = v.y;
            Xs[kk4 * 4 + 2][n] = v.z;
            Xs[kk4 * 4 + 3][n] = v.w;
        }
#pragma unroll
        for (int it = 0; it < 2; ++it) {
            int idx = tid + it * 256;
            int j = idx >> 2, kk4 = idx & 3;
            float4 v = *(const float4*)(W + j * 1152 + k0 + kk4 * 4);
            Ws[kk4 * 4 + 0][j] = v.x;
            Ws[kk4 * 4 + 1][j] = v.y;
            Ws[kk4 * 4 + 2][j] = v.z;
            Ws[kk4 * 4 + 3][j] = v.w;
        }
        __syncthreads();

#pragma unroll
        for (int kk = 0; kk < 16; kk++) {
            float4 xa = *(const float4*)&Xs[kk][tn * 8];
            float4 xb = *(const float4*)&Xs[kk][tn * 8 + 4];
            float4 wa = *(const float4*)&Ws[kk][tj * 8];
            float4 wb = *(const float4*)&Ws[kk][tj * 8 + 4];
            float xv[8] = {xa.x, xa.y, xa.z, xa.w, xb.x, xb.y, xb.z, xb.w};
            float wv[8] = {wa.x, wa.y, wa.z, wa.w, wb.x, wb.y, wb.z, wb.w};
#pragma unroll
            for (int i = 0; i < 8; i++)
#pragma unroll
                for (int j = 0; j < 8; j++) acc[i][j] += xv[i] * wv[j];
        }
        __syncthreads();
    }

    float bv[8];
#pragma unroll
    for (int j = 0; j < 8; j++) bv[j] = bias[tj * 8 + j];
#pragma unroll
    for (int i = 0; i < 8; i++) {
        int n = nbase + tn * 8 + i;
        if (n < N) {
            float* o = g_H + (rowOff + n) * 128 + tj * 8;
            float4 oa, ob;
            oa.x = fmaxf(acc[i][0] + bv[0], 0.f);
            oa.y = fmaxf(acc[i][1] + bv[1], 0.f);
            oa.z = fmaxf(acc[i][2] + bv[2], 0.f);
            oa.w = fmaxf(acc[i][3] + bv[3], 0.f);
            ob.x = fmaxf(acc[i][4] + bv[4], 0.f);
            ob.y = fmaxf(acc[i][5] + bv[5], 0.f);
            ob.z = fmaxf(acc[i][6] + bv[6], 0.f);
            ob.w = fmaxf(acc[i][7] + bv[7], 0.f);
            *(float4*)o       = oa;
            *(float4*)(o + 4) = ob;
        }
    }
}

// ---------------- Stage C: emb GEMM + LayerNorm ----------------
// 64 nodes x 128 outs per block, K=128 (chunks of 32), then row-wise LN.
__global__ __launch_bounds__(256) void emb_kernel(
    const float* __restrict__ embW,   // (10,128,128)
    const float* __restrict__ embB,   // (10,128)
    const float* __restrict__ lng,    // (10,128)
    const float* __restrict__ lnb,    // (10,128)
    const float* __restrict__ dgain,  // (10)
    float* __restrict__ out)
{
    __shared__ float sm[8448];        // Xs[32][68] + Ws[32][132], reused as Y[64][132]
    int tid = threadIdx.x;
    int bid = blockIdx.x;

    int d = 0;
    while (d < 9 && bid >= c_embCum[d + 1]) d++;
    int N = c_SIZE[d];
    int rowOff = c_OFF[d];
    int nb = (bid - c_embCum[d]) * 64;
    const float* src = (d == 0 || d == 9) ? g_G : g_H;
    const float* Wd = embW + d * 128 * 128;

    float* Xs = sm;              // pitch 68
    float* Ws = sm + 32 * 68;    // pitch 132

    float acc[8][4];
#pragma unroll
    for (int i = 0; i < 8; i++)
#pragma unroll
        for (int j = 0; j < 4; j++) acc[i][j] = 0.f;

    int tn = tid & 7, tj = tid >> 3;
    int n0 = tn * 8, j0 = tj * 4;

    for (int k0 = 0; k0 < 128; k0 += 32) {
#pragma unroll
        for (int it = 0; it < 2; ++it) {
            int idx = tid + it * 256;          // 0..511 : 64 nodes x 8 float4
            int n = idx >> 3, k4 = idx & 7;
            float4 v = make_float4(0.f, 0.f, 0.f, 0.f);
            int nl = nb + n;
            if (nl < N) v = *(const float4*)(src + (rowOff + nl) * 128 + k0 + k4 * 4);
            Xs[(k4 * 4 + 0) * 68 + n] = v.x;
            Xs[(k4 * 4 + 1) * 68 + n] = v.y;
            Xs[(k4 * 4 + 2) * 68 + n] = v.z;
            Xs[(k4 * 4 + 3) * 68 + n] = v.w;
        }
#pragma unroll
        for (int it = 0; it < 4; ++it) {
            int idx = tid + it * 256;          // 0..1023 : 128 j x 8 float4
            int j = idx >> 3, k4 = idx & 7;
            float4 v = *(const float4*)(Wd + j * 128 + k0 + k4 * 4);
            Ws[(k4 * 4 + 0) * 132 + j] = v.x;
            Ws[(k4 * 4 + 1) * 132 + j] = v.y;
            Ws[(k4 * 4 + 2) * 132 + j] = v.z;
            Ws[(k4 * 4 + 3) * 132 + j] = v.w;
        }
        __syncthreads();

#pragma unroll
        for (int kk = 0; kk < 32; ++kk) {
            float4 xa = *(const float4*)&Xs[kk * 68 + n0];
            float4 xb = *(const float4*)&Xs[kk * 68 + n0 + 4];
            float4 w  = *(const float4*)&Ws[kk * 132 + j0];
            float xv[8] = {xa.x, xa.y, xa.z, xa.w, xb.x, xb.y, xb.z, xb.w};
            float wv[4] = {w.x, w.y, w.z, w.w};
#pragma unroll
            for (int i = 0; i < 8; i++)
#pragma unroll
                for (int j = 0; j < 4; j++) acc[i][j] += xv[i] * wv[j];
        }
        __syncthreads();
    }

    // Y tile into smem (pitch 132), with bias
    float bb0 = embB[d * 128 + j0], bb1 = embB[d * 128 + j0 + 1];
    float bb2 = embB[d * 128 + j0 + 2], bb3 = embB[d * 128 + j0 + 3];
#pragma unroll
    for (int i = 0; i < 8; i++) {
        float4 o = make_float4(acc[i][0] + bb0, acc[i][1] + bb1,
                               acc[i][2] + bb2, acc[i][3] + bb3);
        *(float4*)&sm[(n0 + i) * 132 + j0] = o;
    }
    __syncthreads();

    // LayerNorm: warp w handles rows w*8..w*8+7; lane owns channels lane*4..+3
    int wrp = tid >> 5, lane = tid & 31;
    float g0 = lng[d * 128 + lane * 4], g1 = lng[d * 128 + lane * 4 + 1];
    float g2 = lng[d * 128 + lane * 4 + 2], g3 = lng[d * 128 + lane * 4 + 3];
    float lb0 = lnb[d * 128 + lane * 4], lb1 = lnb[d * 128 + lane * 4 + 1];
    float lb2 = lnb[d * 128 + lane * 4 + 2], lb3 = lnb[d * 128 + lane * 4 + 3];
    float dgn = dgain[d];

#pragma unroll
    for (int r8 = 0; r8 < 8; ++r8) {
        int r = wrp * 8 + r8;
        float4 y = *(const float4*)&sm[r * 132 + lane * 4];
        float s = y.x + y.y + y.z + y.w;
#pragma unroll
        for (int off = 16; off > 0; off >>= 1)
            s += __shfl_xor_sync(0xffffffffu, s, off);
        float mu = s * (1.f / 128.f);
        float dx = y.x - mu, dy2 = y.y - mu, dz = y.z - mu, dw = y.w - mu;
        float s2 = dx * dx + dy2 * dy2 + dz * dz + dw * dw;
#pragma unroll
        for (int off = 16; off > 0; off >>= 1)
            s2 += __shfl_xor_sync(0xffffffffu, s2, off);
        float var = s2 * (1.f / 128.f);
        float rs = rsqrtf(var + 1e-5f);
        int nl = nb + r;
        if (nl < N) {
            float4 o;
            o.x = dgn * (dx * rs * g0 + lb0);
            o.y = dgn * (dy2 * rs * g1 + lb1);
            o.z = dgn * (dz * rs * g2 + lb2);
            o.w = dgn * (dw * rs * g3 + lb3);
            *(float4*)&out[(rowOff + nl) * 128 + lane * 4] = o;
        }
    }
}

// ---------------- launch ----------------
extern "C" void kernel_launch(void* const* d_in, const int* in_sizes, int n_in,
                              void* d_out, int out_size)
{
    const float* feats = (const float*)d_in[0];
    const float* inW   = (const float*)d_in[1];
    const float* inB   = (const float*)d_in[2];
    const float* convW = (const float*)d_in[3];
    const float* convB = (const float*)d_in[4];
    const float* embW  = (const float*)d_in[5];
    const float* embB  = (const float*)d_in[6];
    const float* lng   = (const float*)d_in[7];
    const float* lnb   = (const float*)d_in[8];
    const float* dg    = (const float*)d_in[9];
    float* out = (float*)d_out;

    static const int OFFS[11] = {0,1,5,21,85,341,1365,5461,21845,87381,349525};
    static const int SZ[10]   = {1,4,16,64,256,1024,4096,16384,65536,262144};

    // Stage A: encode + in_proj -> g_G (all levels)
    enc_kernel<<<(TOTAL + 31) / 32, 256>>>(feats, inW, inB);

    // Stage B: top-down pooling + per-level quadconv
    for (int d = 9; d >= 1; --d) {
        int dst = d - 1;
        int nthr = SZ[dst] * 32;
        pool_kernel<<<(nthr + 255) / 256, 256>>>(dst, (d == 9) ? 1 : 0);
        if (dst >= 1) {
            conv_kernel<<<(SZ[dst] + 127) / 128, 256>>>(
                convW + (long)dst * 128 * 1152, convB + dst * 128,
                SZ[dst], 1 << dst, OFFS[dst]);
        }
    }

    // Stage C: emb + LayerNorm -> out
    emb_kernel<<<5464, 256>>>(embW, embB, lng, lnb, dg, out);
}

// round 13
// speedup vs baseline: 1.6061x; 1.6061x over previous
#include <cuda_runtime.h>
#include <cuda_bf16.h>
#include <stdint.h>
#include <stddef.h>
#include <math.h>

#define TOTAL 349525
#define WELEMS (10 * 128 * 1152)

// ---------------- constants ----------------
__constant__ int c_OFF[11]   = {0,1,5,21,85,341,1365,5461,21845,87381,349525};
__constant__ int c_SIZE[10]  = {1,4,16,64,256,1024,4096,16384,65536,262144};
__constant__ int c_embCum[11]= {0,1,2,3,4,8,24,88,344,1368,5464};

// ---------------- scratch (device globals: allocation-free) ----------------
__device__ float g_G[TOTAL * 128];            // pre-conv accumulator
__device__ float g_H[TOTAL * 128];            // post-conv output per level
__device__ __nv_bfloat16 g_Ghi[TOTAL * 128];  // bf16 hi split of G
__device__ __nv_bfloat16 g_Glo[TOTAL * 128];  // bf16 lo split of G
__device__ __nv_bfloat16 g_Whi[WELEMS];       // bf16 hi split of conv_W
__device__ __nv_bfloat16 g_Wlo[WELEMS];       // bf16 lo split of conv_W

// ---------------- Morton helpers ----------------
__device__ __forceinline__ unsigned deint(unsigned x) {
    x &= 0x55555555u;
    x = (x | (x >> 1)) & 0x33333333u;
    x = (x | (x >> 2)) & 0x0F0F0F0Fu;
    x = (x | (x >> 4)) & 0x00FF00FFu;
    x = (x | (x >> 8)) & 0x0000FFFFu;
    return x;
}
__device__ __forceinline__ unsigned inter(unsigned x) {
    x &= 0xFFFFu;
    x = (x | (x << 8)) & 0x00FF00FFu;
    x = (x | (x << 4)) & 0x0F0F0F0Fu;
    x = (x | (x << 2)) & 0x33333333u;
    x = (x | (x << 1)) & 0x55555555u;
    return x;
}

__device__ __forceinline__ uint32_t smem_u32(const void* p) {
    uint32_t a;
    asm("{ .reg .u64 t; cvta.to.shared.u64 t, %1; cvt.u32.u64 %0, t; }"
        : "=r"(a) : "l"(p));
    return a;
}

// ldmatrix x4 (sm_75+, valid on sm_103 base target)
#define LDSM_X4(r0, r1, r2, r3, addr) \
    asm volatile("ldmatrix.sync.aligned.m8n8.x4.shared.b16 {%0,%1,%2,%3}, [%4];" \
        : "=r"(r0), "=r"(r1), "=r"(r2), "=r"(r3) : "r"(addr))

// mma.sync bf16 (sm_80+, valid on sm_103 base target)
#define MMA16816(c, a, b) \
    asm volatile("mma.sync.aligned.m16n8k16.row.col.f32.bf16.bf16.f32 " \
        "{%0,%1,%2,%3}, {%4,%5,%6,%7}, {%8,%9}, {%0,%1,%2,%3};" \
        : "+f"((c)[0]), "+f"((c)[1]), "+f"((c)[2]), "+f"((c)[3]) \
        : "r"((a)[0]), "r"((a)[1]), "r"((a)[2]), "r"((a)[3]), \
          "r"((b)[0]), "r"((b)[1]))

// ---------------- weight split kernel (once per launch) ----------------
__global__ __launch_bounds__(256) void convW_split_kernel(const float* __restrict__ W)
{
    int i = blockIdx.x * 256 + threadIdx.x;
    if (i < WELEMS) {
        float x = W[i];
        __nv_bfloat16 h = __float2bfloat16(x);
        g_Whi[i] = h;
        g_Wlo[i] = __float2bfloat16(x - __bfloat162float(h));
    }
}

// ---------------- Stage A: pos-encode + in_proj ----------------
__global__ __launch_bounds__(256) void enc_kernel(
    const float* __restrict__ feats,
    const float* __restrict__ W,       // (128,40)
    const float* __restrict__ bias)    // (128)
{
    __shared__ float Xs[40][36];
    __shared__ float Ws[40][128];
    __shared__ float px[32], py[32], pd[32];

    int tid = threadIdx.x;
    int nbase = blockIdx.x * 32;

    if (tid < 32) {
        int g = nbase + tid;
        float fx = 0.f, fy = 0.f, fd = 0.f, ff = 0.f;
        if (g < TOTAL) {
            int d = 0;
            while (d < 9 && g >= c_OFF[d + 1]) d++;
            int li = g - c_OFF[d];
            unsigned ix = deint((unsigned)li);
            unsigned iy = deint(((unsigned)li) >> 1);
            float res = (float)(1 << d);
            fx = ((float)ix + 0.5f) / res;
            fy = ((float)iy + 0.5f) / res;
            fd = (float)d / 9.0f;
            ff = feats[g];
        }
        px[tid] = fx; py[tid] = fy; pd[tid] = fd;
        Xs[0][tid] = ff; Xs[1][tid] = fx; Xs[2][tid] = fy; Xs[3][tid] = fd;
    }
    for (int idx = tid; idx < 128 * 40; idx += 256) {
        Ws[idx % 40][idx / 40] = W[idx];
    }
    __syncthreads();

    for (int idx = tid; idx < 32 * 18; idx += 256) {
        int n = idx & 31;
        int t = idx >> 5;
        int comp = t / 6, f = t % 6;
        float p = (comp == 0) ? px[n] : ((comp == 1) ? py[n] : pd[n]);
        float ang = p * 6.283185307179586f * (float)(1 << f);
        float s, c;
        sincosf(ang, &s, &c);
        Xs[4 + comp * 12 + f][n]     = s;
        Xs[4 + comp * 12 + 6 + f][n] = c;
    }
    __syncthreads();

    int tn = tid & 7, tj = tid >> 3;
    int n0 = tn * 4, j0 = tj * 4;
    float acc[4][4];
#pragma unroll
    for (int i = 0; i < 4; i++)
#pragma unroll
        for (int j = 0; j < 4; j++) acc[i][j] = 0.f;

#pragma unroll
    for (int k = 0; k < 40; k++) {
        float4 x = *(const float4*)&Xs[k][n0];
        float4 w = *(const float4*)&Ws[k][j0];
        float xv[4] = {x.x, x.y, x.z, x.w};
        float wv[4] = {w.x, w.y, w.z, w.w};
#pragma unroll
        for (int i = 0; i < 4; i++)
#pragma unroll
            for (int j = 0; j < 4; j++) acc[i][j] += xv[i] * wv[j];
    }

    float b0 = bias[j0], b1 = bias[j0 + 1], b2 = bias[j0 + 2], b3 = bias[j0 + 3];
#pragma unroll
    for (int i = 0; i < 4; i++) {
        int g = nbase + n0 + i;
        if (g < TOTAL) {
            float4 o = make_float4(acc[i][0] + b0, acc[i][1] + b1,
                                   acc[i][2] + b2, acc[i][3] + b3);
            *(float4*)&g_G[g * 128 + j0] = o;
        }
    }
}

// ---------------- Stage B1: pooling + bf16 split ----------------
__global__ __launch_bounds__(256) void pool_kernel(int dst, int srcIsG)
{
    int N = c_SIZE[dst];
    int idx = blockIdx.x * 256 + threadIdx.x;
    if (idx >= N * 32) return;
    int n = idx >> 5, c4 = idx & 31;
    const float* src = srcIsG ? g_G : g_H;
    const float* s0 = src + (c_OFF[dst + 1] + n * 4) * 128 + c4 * 4;
    float4 a = *(const float4*)(s0);
    float4 b = *(const float4*)(s0 + 128);
    float4 c = *(const float4*)(s0 + 256);
    float4 d = *(const float4*)(s0 + 384);
    int grow = c_OFF[dst] + n;
    float* dp = g_G + grow * 128 + c4 * 4;
    float4 g = *(float4*)dp;
    g.x += 0.25f * (a.x + b.x + c.x + d.x);
    g.y += 0.25f * (a.y + b.y + c.y + d.y);
    g.z += 0.25f * (a.z + b.z + c.z + d.z);
    g.w += 0.25f * (a.w + b.w + c.w + d.w);
    *(float4*)dp = g;

    // bf16 hi/lo split for tensor-core conv
    float v[4] = {g.x, g.y, g.z, g.w};
    int e = grow * 128 + c4 * 4;
#pragma unroll
    for (int q = 0; q < 4; q += 2) {
        __nv_bfloat16 h0 = __float2bfloat16(v[q]);
        __nv_bfloat16 h1 = __float2bfloat16(v[q + 1]);
        __nv_bfloat16 l0 = __float2bfloat16(v[q] - __bfloat162float(h0));
        __nv_bfloat16 l1 = __float2bfloat16(v[q + 1] - __bfloat162float(h1));
        *(__nv_bfloat162*)&g_Ghi[e + q] = __nv_bfloat162(h0, h1);
        *(__nv_bfloat162*)&g_Glo[e + q] = __nv_bfloat162(l0, l1);
    }
}

// ---------------- Stage B2: quadconv via mma.sync (legacy HMMA path) ----------------
// CTA: 128 nodes x 128 outputs. 8 warps in 2(M) x 4(N); warp tile 64x32.
// K = 9 taps x 128 ch = 1152, chunks of 32. Split-bf16 3-term MMA.
#define XPITCH 40   // bf16 pitch (32 data + 8 pad) -> conflict-free ldmatrix

__global__ __launch_bounds__(256) void conv_mma_kernel(
    const float* __restrict__ bias, int N, int res, int rowOff, int lvl)
{
    __shared__ __align__(16) __nv_bfloat16 sXh[128][XPITCH];
    __shared__ __align__(16) __nv_bfloat16 sXl[128][XPITCH];
    __shared__ __align__(16) __nv_bfloat16 sWh[128][XPITCH];
    __shared__ __align__(16) __nv_bfloat16 sWl[128][XPITCH];
    __shared__ int nIdx[1152];

    int tid = threadIdx.x;
    int wid = tid >> 5, lane = tid & 31;
    int nbase = blockIdx.x * 128;

    // neighbor indices for this CTA's 128 nodes
    for (int idx = tid; idx < 1152; idx += 256) {
        int n = idx / 9, p = idx % 9;
        int node = nbase + n;
        int val = -1;
        if (node < N) {
            int ix = (int)deint((unsigned)node);
            int iy = (int)deint(((unsigned)node) >> 1);
            int nx = ix + (p % 3) - 1;
            int ny = iy + (p / 3) - 1;
            if (nx >= 0 && nx < res && ny >= 0 && ny < res)
                val = (int)(inter((unsigned)nx) | (inter((unsigned)ny) << 1));
        }
        nIdx[idx] = val;
    }
    __syncthreads();

    int warp_m = (wid & 1) * 64;   // M offset of warp tile
    int warp_n = (wid >> 1) * 32;  // N offset of warp tile

    float acc[4][4][4];
#pragma unroll
    for (int a = 0; a < 4; a++)
#pragma unroll
        for (int b = 0; b < 4; b++)
#pragma unroll
            for (int q = 0; q < 4; q++) acc[a][b][q] = 0.f;

    const __nv_bfloat16* Wh = g_Whi + (size_t)lvl * 128 * 1152;
    const __nv_bfloat16* Wl = g_Wlo + (size_t)lvl * 128 * 1152;

    for (int i = 0; i < 36; i++) {
        int p = i >> 2, c0 = (i & 3) << 5;

        // fill the 4 tiles: 2048 uint4 total, 8 per thread
#pragma unroll
        for (int t = 0; t < 8; t++) {
            int idx = tid + t * 256;           // 0..2047
            int tile = idx >> 9;               // 0:Xh 1:Xl 2:Wh 3:Wl
            int r = (idx >> 2) & 127;
            int q = idx & 3;                   // 16B chunk within 32-bf16 row
            if (tile < 2) {
                int srcn = nIdx[r * 9 + p];
                uint4 v = make_uint4(0, 0, 0, 0);
                if (srcn >= 0) {
                    const __nv_bfloat16* src = (tile == 0) ? g_Ghi : g_Glo;
                    v = *(const uint4*)(src + (size_t)(rowOff + srcn) * 128 + c0 + q * 8);
                }
                __nv_bfloat16* dst = (tile == 0) ? &sXh[r][q * 8] : &sXl[r][q * 8];
                *(uint4*)dst = v;
            } else {
                const __nv_bfloat16* src = (tile == 2) ? Wh : Wl;
                uint4 v = *(const uint4*)(src + (size_t)r * 1152 + p * 128 + c0 + q * 8);
                __nv_bfloat16* dst = (tile == 2) ? &sWh[r][q * 8] : &sWl[r][q * 8];
                *(uint4*)dst = v;
            }
        }
        __syncthreads();

#pragma unroll
        for (int ks = 0; ks < 2; ks++) {
            int kb = ks * 16;
            // A fragments: 4 M-atoms x (hi,lo), ldmatrix.x4 each
            uint32_t ah[4][4], al[4][4];
            int arow = warp_m + (lane & 15);
            int acol = kb + ((lane >> 4) << 3);
#pragma unroll
            for (int a = 0; a < 4; a++) {
                uint32_t adh = smem_u32(&sXh[arow + a * 16][acol]);
                LDSM_X4(ah[a][0], ah[a][1], ah[a][2], ah[a][3], adh);
                uint32_t adl = smem_u32(&sXl[arow + a * 16][acol]);
                LDSM_X4(al[a][0], al[a][1], al[a][2], al[a][3], adl);
            }
            // B fragments: 4 N-atoms x (hi,lo); one ldmatrix.x4 covers 2 N-atoms
            uint32_t bh[4][2], bl[4][2];
            int jrow0 = warp_n + ((lane >> 4) << 3) + (lane & 7);
            int kcol = kb + (((lane >> 3) & 1) << 3);
#pragma unroll
            for (int g = 0; g < 2; g++) {
                uint32_t bdh = smem_u32(&sWh[jrow0 + g * 16][kcol]);
                LDSM_X4(bh[2 * g][0], bh[2 * g][1], bh[2 * g + 1][0], bh[2 * g + 1][1], bdh);
                uint32_t bdl = smem_u32(&sWl[jrow0 + g * 16][kcol]);
                LDSM_X4(bl[2 * g][0], bl[2 * g][1], bl[2 * g + 1][0], bl[2 * g + 1][1], bdl);
            }
            // 3-term split MMA: hi*hi + hi*lo + lo*hi
#pragma unroll
            for (int a = 0; a < 4; a++)
#pragma unroll
                for (int b = 0; b < 4; b++) {
                    MMA16816(acc[a][b], ah[a], bh[b]);
                    MMA16816(acc[a][b], ah[a], bl[b]);
                    MMA16816(acc[a][b], al[a], bh[b]);
                }
        }
        __syncthreads();
    }

    // epilogue: bias + relu -> g_H
#pragma unroll
    for (int a = 0; a < 4; a++) {
        int r0 = warp_m + a * 16 + (lane >> 2);
#pragma unroll
        for (int b = 0; b < 4; b++) {
            int col = warp_n + b * 8 + ((lane & 3) << 1);
            float bv0 = bias[col], bv1 = bias[col + 1];
            int node0 = nbase + r0;
            if (node0 < N) {
                float* o = g_H + (size_t)(rowOff + node0) * 128 + col;
                o[0] = fmaxf(acc[a][b][0] + bv0, 0.f);
                o[1] = fmaxf(acc[a][b][1] + bv1, 0.f);
            }
            int node1 = node0 + 8;
            if (node1 < N) {
                float* o = g_H + (size_t)(rowOff + node1) * 128 + col;
                o[0] = fmaxf(acc[a][b][2] + bv0, 0.f);
                o[1] = fmaxf(acc[a][b][3] + bv1, 0.f);
            }
        }
    }
}

// ---------------- Stage C: emb GEMM + LayerNorm ----------------
__global__ __launch_bounds__(256) void emb_kernel(
    const float* __restrict__ embW,
    const float* __restrict__ embB,
    const float* __restrict__ lng,
    const float* __restrict__ lnb,
    const float* __restrict__ dgain,
    float* __restrict__ out)
{
    __shared__ float sm[8448];
    int tid = threadIdx.x;
    int bid = blockIdx.x;

    int d = 0;
    while (d < 9 && bid >= c_embCum[d + 1]) d++;
    int N = c_SIZE[d];
    int rowOff = c_OFF[d];
    int nb = (bid - c_embCum[d]) * 64;
    const float* src = (d == 0 || d == 9) ? g_G : g_H;
    const float* Wd = embW + d * 128 * 128;

    float* Xs = sm;
    float* Ws = sm + 32 * 68;

    float acc[8][4];
#pragma unroll
    for (int i = 0; i < 8; i++)
#pragma unroll
        for (int j = 0; j < 4; j++) acc[i][j] = 0.f;

    int tn = tid & 7, tj = tid >> 3;
    int n0 = tn * 8, j0 = tj * 4;

    for (int k0 = 0; k0 < 128; k0 += 32) {
#pragma unroll
        for (int it = 0; it < 2; ++it) {
            int idx = tid + it * 256;
            int n = idx >> 3, k4 = idx & 7;
            float4 v = make_float4(0.f, 0.f, 0.f, 0.f);
            int nl = nb + n;
            if (nl < N) v = *(const float4*)(src + (rowOff + nl) * 128 + k0 + k4 * 4);
            Xs[(k4 * 4 + 0) * 68 + n] = v.x;
            Xs[(k4 * 4 + 1) * 68 + n] = v.y;
            Xs[(k4 * 4 + 2) * 68 + n] = v.z;
            Xs[(k4 * 4 + 3) * 68 + n] = v.w;
        }
#pragma unroll
        for (int it = 0; it < 4; ++it) {
            int idx = tid + it * 256;
            int j = idx >> 3, k4 = idx & 7;
            float4 v = *(const float4*)(Wd + j * 128 + k0 + k4 * 4);
            Ws[(k4 * 4 + 0) * 132 + j] = v.x;
            Ws[(k4 * 4 + 1) * 132 + j] = v.y;
            Ws[(k4 * 4 + 2) * 132 + j] = v.z;
            Ws[(k4 * 4 + 3) * 132 + j] = v.w;
        }
        __syncthreads();

#pragma unroll
        for (int kk = 0; kk < 32; ++kk) {
            float4 xa = *(const float4*)&Xs[kk * 68 + n0];
            float4 xb = *(const float4*)&Xs[kk * 68 + n0 + 4];
            float4 w  = *(const float4*)&Ws[kk * 132 + j0];
            float xv[8] = {xa.x, xa.y, xa.z, xa.w, xb.x, xb.y, xb.z, xb.w};
            float wv[4] = {w.x, w.y, w.z, w.w};
#pragma unroll
            for (int i = 0; i < 8; i++)
#pragma unroll
                for (int j = 0; j < 4; j++) acc[i][j] += xv[i] * wv[j];
        }
        __syncthreads();
    }

    float bb0 = embB[d * 128 + j0], bb1 = embB[d * 128 + j0 + 1];
    float bb2 = embB[d * 128 + j0 + 2], bb3 = embB[d * 128 + j0 + 3];
#pragma unroll
    for (int i = 0; i < 8; i++) {
        float4 o = make_float4(acc[i][0] + bb0, acc[i][1] + bb1,
                               acc[i][2] + bb2, acc[i][3] + bb3);
        *(float4*)&sm[(n0 + i) * 132 + j0] = o;
    }
    __syncthreads();

    int wrp = tid >> 5, lane = tid & 31;
    float g0 = lng[d * 128 + lane * 4], g1 = lng[d * 128 + lane * 4 + 1];
    float g2 = lng[d * 128 + lane * 4 + 2], g3 = lng[d * 128 + lane * 4 + 3];
    float lb0 = lnb[d * 128 + lane * 4], lb1 = lnb[d * 128 + lane * 4 + 1];
    float lb2 = lnb[d * 128 + lane * 4 + 2], lb3 = lnb[d * 128 + lane * 4 + 3];
    float dgn = dgain[d];

#pragma unroll
    for (int r8 = 0; r8 < 8; ++r8) {
        int r = wrp * 8 + r8;
        float4 y = *(const float4*)&sm[r * 132 + lane * 4];
        float s = y.x + y.y + y.z + y.w;
#pragma unroll
        for (int off = 16; off > 0; off >>= 1)
            s += __shfl_xor_sync(0xffffffffu, s, off);
        float mu = s * (1.f / 128.f);
        float dx = y.x - mu, dy2 = y.y - mu, dz = y.z - mu, dw = y.w - mu;
        float s2 = dx * dx + dy2 * dy2 + dz * dz + dw * dw;
#pragma unroll
        for (int off = 16; off > 0; off >>= 1)
            s2 += __shfl_xor_sync(0xffffffffu, s2, off);
        float var = s2 * (1.f / 128.f);
        float rs = rsqrtf(var + 1e-5f);
        int nl = nb + r;
        if (nl < N) {
            float4 o;
            o.x = dgn * (dx * rs * g0 + lb0);
            o.y = dgn * (dy2 * rs * g1 + lb1);
            o.z = dgn * (dz * rs * g2 + lb2);
            o.w = dgn * (dw * rs * g3 + lb3);
            *(float4*)&out[(rowOff + nl) * 128 + lane * 4] = o;
        }
    }
}

// ---------------- launch ----------------
extern "C" void kernel_launch(void* const* d_in, const int* in_sizes, int n_in,
                              void* d_out, int out_size)
{
    const float* feats = (const float*)d_in[0];
    const float* inW   = (const float*)d_in[1];
    const float* inB   = (const float*)d_in[2];
    const float* convW = (const float*)d_in[3];
    const float* convB = (const float*)d_in[4];
    const float* embW  = (const float*)d_in[5];
    const float* embB  = (const float*)d_in[6];
    const float* lng   = (const float*)d_in[7];
    const float* lnb   = (const float*)d_in[8];
    const float* dg    = (const float*)d_in[9];
    float* out = (float*)d_out;

    static const int OFFS[11] = {0,1,5,21,85,341,1365,5461,21845,87381,349525};
    static const int SZ[10]   = {1,4,16,64,256,1024,4096,16384,65536,262144};

    // Stage A: encode + in_proj -> g_G ; weight bf16 split
    enc_kernel<<<(TOTAL + 31) / 32, 256>>>(feats, inW, inB);
    convW_split_kernel<<<(WELEMS + 255) / 256, 256>>>(convW);

    // Stage B: top-down pooling (+G split) + tensor-core quadconv
    for (int d = 9; d >= 1; --d) {
        int dst = d - 1;
        int nthr = SZ[dst] * 32;
        pool_kernel<<<(nthr + 255) / 256, 256>>>(dst, (d == 9) ? 1 : 0);
        if (dst >= 1) {
            conv_mma_kernel<<<(SZ[dst] + 127) / 128, 256>>>(
                convB + dst * 128, SZ[dst], 1 << dst, OFFS[dst], dst);
        }
    }

    // Stage C: emb + LayerNorm -> out
    emb_kernel<<<5464, 256>>>(embW, embB, lng, lnb, dg, out);
}